// round 3
// baseline (speedup 1.0000x reference)
#include <cuda_runtime.h>
#include <cstdint>
#include <cstddef>

#define DEVFN __device__ __forceinline__

static constexpr int   BTOK = 65536;   // B*S
static constexpr int   DM   = 512;     // d_model
static constexpr int   DF   = 2048;    // d_ff
static constexpr float EPSF = 1e-5f;

static constexpr int STAGES  = 4;
static constexpr int STG     = 16384;          // per stage: A 8KB + B 8KB
static constexpr int SMEM_SZ = STAGES * STG;   // 64 KB

// ---------------- device scratch (static = allowed) ----------------
__device__ uint4  g_xq_raw[(size_t)BTOK * DM / 16];   //  32 MB s8 xq
__device__ uint4  g_wu_raw[(size_t)DF * DM / 16];     //   1 MB s8 ternary w_up
__device__ uint4  g_wd_raw[(size_t)DM * DF / 16];     //   1 MB s8 ternary w_down
__device__ uint4  g_h_raw [(size_t)BTOK * DF / 16];   // 128 MB s8 h (0..127)
__device__ uint4  g_hq_raw[(size_t)BTOK * DF / 16];   // 128 MB s8 hq (0..127)
__device__ float  g_xs[BTOK];       // per-token 127/amax_clipped
__device__ int    g_rowmax[BTOK];   // per-token max int of h
__device__ float  g_hs[BTOK];       // per-token hmax_clipped/127
__device__ double g_part[512];
__device__ float  g_ws[2];          // w_scale up / down

// ---------------- helpers ----------------
DEVFN uint32_t smem_u32(const void* p) {
    uint32_t a;
    asm("{ .reg .u64 t; cvta.to.shared.u64 t, %1; cvt.u32.u64 %0, t; }" : "=r"(a) : "l"(p));
    return a;
}
DEVFN void cpasync16(uint32_t dst, const void* src) {
    asm volatile("cp.async.cg.shared.global [%0], [%1], 16;" :: "r"(dst), "l"(src));
}
#define CP_COMMIT() asm volatile("cp.async.commit_group;" ::: "memory")
#define CP_WAIT(n)  asm volatile("cp.async.wait_group %0;" :: "n"(n) : "memory")

#define LDMATRIX_X4(r, addr) \
    asm volatile("ldmatrix.sync.aligned.m8n8.x4.shared.b16 {%0,%1,%2,%3}, [%4];" \
        : "=r"((r)[0]), "=r"((r)[1]), "=r"((r)[2]), "=r"((r)[3]) : "r"(addr))

#define IMMA(c, a, b0_, b1_) \
    asm volatile("mma.sync.aligned.m16n8k32.row.col.s32.s8.s8.s32 " \
        "{%0,%1,%2,%3},{%4,%5,%6,%7},{%8,%9},{%0,%1,%2,%3};" \
        : "+r"((c)[0]), "+r"((c)[1]), "+r"((c)[2]), "+r"((c)[3]) \
        : "r"((a)[0]), "r"((a)[1]), "r"((a)[2]), "r"((a)[3]), "r"(b0_), "r"(b1_))

// ---------------- small kernels ----------------
__global__ void k_absmean(const float* wu, const float* wd) {
    __shared__ double sd[256];
    int b = blockIdx.x, t = threadIdx.x;
    const float* src = (b < 256) ? wu : wd;
    int bb = b & 255;
    double a = 0.0;
    for (int i = bb * 256 + t; i < DF * DM; i += 65536) a += (double)fabsf(src[i]);
    sd[t] = a; __syncthreads();
    for (int o = 128; o; o >>= 1) { if (t < o) sd[t] += sd[t + o]; __syncthreads(); }
    if (t == 0) g_part[b] = sd[0];
}

__global__ void k_final() {
    __shared__ double sd[256];
    int t = threadIdx.x;
    sd[t] = g_part[t]; __syncthreads();
    for (int o = 128; o; o >>= 1) { if (t < o) sd[t] += sd[t + o]; __syncthreads(); }
    if (t == 0) g_ws[0] = fmaxf((float)(sd[0] / (double)(DF * DM)), EPSF);
    __syncthreads();
    sd[t] = g_part[256 + t]; __syncthreads();
    for (int o = 128; o; o >>= 1) { if (t < o) sd[t] += sd[t + o]; __syncthreads(); }
    if (t == 0) g_ws[1] = fmaxf((float)(sd[0] / (double)(DF * DM)), EPSF);
}

__global__ void k_tern(const float* wu, const float* wd) {
    int i = blockIdx.x * 256 + threadIdx.x;
    float ws, v; int8_t* dst;
    if (i < DF * DM) { ws = g_ws[0]; v = wu[i]; dst = (int8_t*)g_wu_raw + i; }
    else             { ws = g_ws[1]; v = wd[i - DF * DM]; dst = (int8_t*)g_wd_raw + (i - DF * DM); }
    float q = fminf(fmaxf(rintf(v / ws), -1.f), 1.f);
    *dst = (int8_t)(int)q;
}

__global__ void k_xquant(const float* x) {
    int wid = threadIdx.x >> 5, lane = threadIdx.x & 31;
    int row = blockIdx.x * 8 + wid;
    const float4* xr = (const float4*)(x + (size_t)row * DM);
    float4 v[4]; float am = 0.f;
#pragma unroll
    for (int j = 0; j < 4; j++) {
        v[j] = xr[lane + 32 * j];
        am = fmaxf(am, fmaxf(fmaxf(fabsf(v[j].x), fabsf(v[j].y)), fmaxf(fabsf(v[j].z), fabsf(v[j].w))));
    }
#pragma unroll
    for (int o = 16; o; o >>= 1) am = fmaxf(am, __shfl_xor_sync(0xffffffffu, am, o));
    float xsc = 127.0f / fmaxf(am, EPSF);
    if (lane == 0) { g_xs[row] = xsc; g_rowmax[row] = 0; }
    uchar4* op = (uchar4*)((int8_t*)g_xq_raw + (size_t)row * DM);
#pragma unroll
    for (int j = 0; j < 4; j++) {
        int q0 = (int)fminf(fmaxf(rintf(v[j].x * xsc), -128.f), 127.f);
        int q1 = (int)fminf(fmaxf(rintf(v[j].y * xsc), -128.f), 127.f);
        int q2 = (int)fminf(fmaxf(rintf(v[j].z * xsc), -128.f), 127.f);
        int q3 = (int)fminf(fmaxf(rintf(v[j].w * xsc), -128.f), 127.f);
        op[lane + 32 * j] = make_uchar4((unsigned char)q0, (unsigned char)q1,
                                        (unsigned char)q2, (unsigned char)q3);
    }
}

__global__ void k_requant() {
    int wid = threadIdx.x >> 5, lane = threadIdx.x & 31;
    int row = blockIdx.x * 8 + wid;
    float clipped = fmaxf((float)g_rowmax[row], EPSF);
    float s = 127.0f / clipped;
    if (lane == 0) g_hs[row] = clipped / 127.0f;
    const uint4* hr = (const uint4*)((const char*)g_h_raw + (size_t)row * DF);
    uint4* op = (uint4*)((char*)g_hq_raw + (size_t)row * DF);
#pragma unroll
    for (int j = 0; j < 4; j++) {
        uint4 w = hr[lane + 32 * j];
        uint32_t in[4] = {w.x, w.y, w.z, w.w};
        uint32_t out[4];
#pragma unroll
        for (int k = 0; k < 4; k++) {
            uint32_t b = in[k], o = 0;
#pragma unroll
            for (int u = 0; u < 4; u++) {
                float hv = (float)((b >> (8 * u)) & 0xFF);            // h in 0..127
                uint32_t q = (uint32_t)(int)fminf(rintf(hv * s), 127.f);
                o |= (q & 0xFF) << (8 * u);
            }
            out[k] = o;
        }
        op[lane + 32 * j] = make_uint4(out[0], out[1], out[2], out[3]);
    }
}

// ---------------- int8 GEMM: C[128x128] = A[128,K] * B[128,K]^T ----------------
// warp grid 4(M) x 2(N); warp tile 32x64; mma m16n8k32 s8.s8.s32
__global__ void __launch_bounds__(256) k_gemm(int K, int ntiles, int mode, float* OUT) {
    extern __shared__ char smem[];
    const uint32_t sb = smem_u32(smem);
    const int tid = threadIdx.x, lane = tid & 31, wid = tid >> 5;
    const int bid = blockIdx.x, mt = bid / ntiles, nt = bid % ntiles;
    const int m0 = mt * 128, n0 = nt * 128;
    const int wm = wid >> 1, wn = wid & 1;

    const int8_t* Ag = (mode == 1) ? (const int8_t*)g_xq_raw : (const int8_t*)g_hq_raw;
    const int8_t* Bg = (mode == 1) ? (const int8_t*)g_wu_raw : (const int8_t*)g_wd_raw;

    // ---- cp.async slots: 2 A granules + 2 B granules (16B) per thread ----
    const int8_t* srcA[2]; const int8_t* srcB[2];
    uint32_t dstA[2], dstB[2];
#pragma unroll
    for (int i = 0; i < 2; i++) {
        int G = tid + i * 256;                         // 0..511
        int r = G >> 2, ck = G & 3;                    // row 0..127, 16B chunk 0..3
        uint32_t phys = ((uint32_t)(ck ^ ((r >> 1) & 3))) << 4;
        dstA[i] = (uint32_t)r * 64 + phys;
        dstB[i] = 8192u + (uint32_t)r * 64 + phys;
        srcA[i] = Ag + (size_t)(m0 + r) * K + ck * 16;
        srcB[i] = Bg + (size_t)(n0 + r) * K + ck * 16;
    }

    // ---- ldmatrix lane precompute ----
    const int matrow = lane & 7, matsel = lane >> 3;
    const uint32_t kb16 = (uint32_t)(matsel >> 1);     // 16B half within k32
    const int r8 = (matsel & 1) * 8;
    uint32_t aTerm[2], aSw[2], bTerm[4], bSw[4];
#pragma unroll
    for (int f = 0; f < 2; f++) {
        int r = wm * 32 + f * 16 + r8 + matrow;
        aTerm[f] = (uint32_t)r * 64; aSw[f] = (uint32_t)((r >> 1) & 3);
    }
#pragma unroll
    for (int p = 0; p < 4; p++) {
        int r = wn * 64 + p * 16 + r8 + matrow;
        bTerm[p] = (uint32_t)r * 64; bSw[p] = (uint32_t)((r >> 1) & 3);
    }

    int acc[2][8][4];
#pragma unroll
    for (int f = 0; f < 2; f++)
#pragma unroll
        for (int j = 0; j < 8; j++)
#pragma unroll
            for (int k = 0; k < 4; k++) acc[f][j][k] = 0;

    const int nch = K / 64;
    // prologue: 3 stages
#pragma unroll
    for (int c = 0; c < 3; c++) {
        uint32_t base = sb + (uint32_t)(c & 3) * STG;
        size_t ko = (size_t)c * 64;
#pragma unroll
        for (int i = 0; i < 2; i++) cpasync16(base + dstA[i], srcA[i] + ko);
#pragma unroll
        for (int i = 0; i < 2; i++) cpasync16(base + dstB[i], srcB[i] + ko);
        CP_COMMIT();
    }

    for (int c = 0; c < nch; c++) {
        CP_WAIT(2);
        __syncthreads();
        // ---- compute stage c&3 : two k32 steps ----
        uint32_t base = sb + (uint32_t)(c & 3) * STG;
#pragma unroll
        for (int ks = 0; ks < 2; ks++) {
            uint32_t av[2][4], bv[4][4];
            uint32_t ck = (uint32_t)(ks * 2) + kb16;
#pragma unroll
            for (int f = 0; f < 2; f++) {
                uint32_t ad = base + aTerm[f] + ((ck ^ aSw[f]) << 4);
                LDMATRIX_X4(av[f], ad);
            }
#pragma unroll
            for (int p = 0; p < 4; p++) {
                uint32_t bd = base + 8192u + bTerm[p] + ((ck ^ bSw[p]) << 4);
                LDMATRIX_X4(bv[p], bd);
            }
#pragma unroll
            for (int f = 0; f < 2; f++)
#pragma unroll
                for (int j = 0; j < 8; j++) {
                    int p = j >> 1, o = j & 1;
                    IMMA(acc[f][j], av[f], bv[p][o], bv[p][o + 2]);
                }
        }
        // ---- issue next load ----
        int nx = c + 3;
        if (nx < nch) {
            uint32_t nb = sb + (uint32_t)(nx & 3) * STG;
            size_t ko = (size_t)nx * 64;
#pragma unroll
            for (int i = 0; i < 2; i++) cpasync16(nb + dstA[i], srcA[i] + ko);
#pragma unroll
            for (int i = 0; i < 2; i++) cpasync16(nb + dstB[i], srcB[i] + ko);
        }
        CP_COMMIT();
    }
    CP_WAIT(0);
    __syncthreads();

    // ---- epilogue ----
    const int g = lane >> 2, q4 = lane & 3;     // group row, in-group col pair
    if (mode == 1) {
        const float ws0 = g_ws[0];
        int lmax[2][2] = {{0, 0}, {0, 0}};
        int8_t* tile = (int8_t*)smem;           // 128x128 s8 staging
#pragma unroll
        for (int f = 0; f < 2; f++) {
            int rl0 = wm * 32 + f * 16 + g;
            float sc0 = ws0 / g_xs[m0 + rl0];
            float sc1 = ws0 / g_xs[m0 + rl0 + 8];
#pragma unroll
            for (int j = 0; j < 8; j++) {
                int col = wn * 64 + j * 8 + q4 * 2;
                int q0 = (int)fminf(rintf(fmaxf((float)acc[f][j][0] * sc0, 0.f)), 127.f);
                int q1 = (int)fminf(rintf(fmaxf((float)acc[f][j][1] * sc0, 0.f)), 127.f);
                int q2 = (int)fminf(rintf(fmaxf((float)acc[f][j][2] * sc1, 0.f)), 127.f);
                int q3 = (int)fminf(rintf(fmaxf((float)acc[f][j][3] * sc1, 0.f)), 127.f);
                lmax[f][0] = max(lmax[f][0], max(q0, q1));
                lmax[f][1] = max(lmax[f][1], max(q2, q3));
                *(char2*)(tile + rl0 * 128 + col)       = make_char2((char)q0, (char)q1);
                *(char2*)(tile + (rl0 + 8) * 128 + col) = make_char2((char)q2, (char)q3);
            }
        }
        // reduce row max across the 4 lanes of a group, then atomicMax
#pragma unroll
        for (int f = 0; f < 2; f++)
#pragma unroll
            for (int h = 0; h < 2; h++) {
                int v = lmax[f][h];
                v = max(v, __shfl_xor_sync(0xffffffffu, v, 1));
                v = max(v, __shfl_xor_sync(0xffffffffu, v, 2));
                if (q4 == 0) {
                    int row = m0 + wm * 32 + f * 16 + g + h * 8;
                    atomicMax(&g_rowmax[row], v);
                }
            }
        __syncthreads();
        // coalesced copy smem tile -> gmem h
        int8_t* hg = (int8_t*)g_h_raw;
#pragma unroll
        for (int i = 0; i < 4; i++) {
            int G = tid + i * 256;               // 0..1023
            int r = G >> 3, ch = G & 7;
            uint4 v = *(uint4*)(tile + r * 128 + ch * 16);
            *(uint4*)(hg + (size_t)(m0 + r) * DF + n0 + ch * 16) = v;
        }
    } else {
        const float ws1 = g_ws[1];
        const int ncols = ntiles * 128;
#pragma unroll
        for (int f = 0; f < 2; f++) {
            int rg0 = m0 + wm * 32 + f * 16 + g;
            float sc0 = ws1 * g_hs[rg0];
            float sc1 = ws1 * g_hs[rg0 + 8];
            float* o0 = OUT + (size_t)rg0 * ncols + n0 + wn * 64 + q4 * 2;
            float* o1 = OUT + (size_t)(rg0 + 8) * ncols + n0 + wn * 64 + q4 * 2;
#pragma unroll
            for (int j = 0; j < 8; j++) {
                float2 v0 = make_float2((float)acc[f][j][0] * sc0, (float)acc[f][j][1] * sc0);
                float2 v1 = make_float2((float)acc[f][j][2] * sc1, (float)acc[f][j][3] * sc1);
                *(float2*)(o0 + j * 8) = v0;
                *(float2*)(o1 + j * 8) = v1;
            }
        }
    }
}

// ---------------- launch ----------------
extern "C" void kernel_launch(void* const* d_in, const int* in_sizes, int n_in,
                              void* d_out, int out_size) {
    const float* x  = (const float*)d_in[0];
    const float* wu = (const float*)d_in[1];
    const float* wd = (const float*)d_in[2];
    float* out = (float*)d_out;

    cudaFuncSetAttribute(k_gemm, cudaFuncAttributeMaxDynamicSharedMemorySize, SMEM_SZ);

    k_absmean<<<512, 256>>>(wu, wd);
    k_final<<<1, 256>>>();
    k_tern<<<(2 * DF * DM) / 256, 256>>>(wu, wd);
    k_xquant<<<BTOK / 8, 256>>>(x);
    k_gemm<<<(BTOK / 128) * (DF / 128), 256, SMEM_SZ>>>(DM, DF / 128, 1, nullptr);
    k_requant<<<BTOK / 8, 256>>>();
    k_gemm<<<(BTOK / 128) * (DM / 128), 256, SMEM_SZ>>>(DF, DM / 128, 2, out);
}

// round 4
// speedup vs baseline: 1.0002x; 1.0002x over previous
#include <cuda_runtime.h>
#include <cstdint>
#include <cstddef>

#define DEVFN __device__ __forceinline__

static constexpr int   BTOK = 65536;   // B*S
static constexpr int   DM   = 512;     // d_model
static constexpr int   DF   = 2048;    // d_ff
static constexpr float EPSF = 1e-5f;

static constexpr int STAGES  = 4;
static constexpr int STG     = 16384;          // per stage: A 8KB + B 8KB
static constexpr int SMEM_SZ = STAGES * STG;   // 64 KB

// ---------------- device scratch (static = allowed) ----------------
__device__ uint4  g_xq_raw[(size_t)BTOK * DM / 16];   //  32 MB s8 xq
__device__ uint4  g_wu_raw[(size_t)DF * DM / 16];     //   1 MB s8 ternary w_up
__device__ uint4  g_wd_raw[(size_t)DM * DF / 16];     //   1 MB s8 ternary w_down
__device__ uint4  g_h_raw [(size_t)BTOK * DF / 16];   // 128 MB s8 h (0..127)
__device__ uint4  g_hq_raw[(size_t)BTOK * DF / 16];   // 128 MB s8 hq (0..127)
__device__ float  g_xs[BTOK];       // per-token 127/amax_clipped
__device__ int    g_rowmax[BTOK];   // per-token max int of h
__device__ float  g_hs[BTOK];       // per-token hmax_clipped/127
__device__ double g_part[512];
__device__ float  g_ws[2];          // w_scale up / down

// ---------------- helpers ----------------
DEVFN uint32_t smem_u32(const void* p) {
    uint32_t a;
    asm("{ .reg .u64 t; cvta.to.shared.u64 t, %1; cvt.u32.u64 %0, t; }" : "=r"(a) : "l"(p));
    return a;
}
DEVFN void cpasync16(uint32_t dst, const void* src) {
    asm volatile("cp.async.cg.shared.global [%0], [%1], 16;" :: "r"(dst), "l"(src));
}
#define CP_COMMIT() asm volatile("cp.async.commit_group;" ::: "memory")
#define CP_WAIT(n)  asm volatile("cp.async.wait_group %0;" :: "n"(n) : "memory")

#define LDMATRIX_X4(r, addr) \
    asm volatile("ldmatrix.sync.aligned.m8n8.x4.shared.b16 {%0,%1,%2,%3}, [%4];" \
        : "=r"((r)[0]), "=r"((r)[1]), "=r"((r)[2]), "=r"((r)[3]) : "r"(addr))

#define IMMA(c, a, b0_, b1_) \
    asm volatile("mma.sync.aligned.m16n8k32.row.col.s32.s8.s8.s32 " \
        "{%0,%1,%2,%3},{%4,%5,%6,%7},{%8,%9},{%0,%1,%2,%3};" \
        : "+r"((c)[0]), "+r"((c)[1]), "+r"((c)[2]), "+r"((c)[3]) \
        : "r"((a)[0]), "r"((a)[1]), "r"((a)[2]), "r"((a)[3]), "r"(b0_), "r"(b1_))

// ---------------- small kernels ----------------
__global__ void k_absmean(const float* wu, const float* wd) {
    __shared__ double sd[256];
    int b = blockIdx.x, t = threadIdx.x;
    const float* src = (b < 256) ? wu : wd;
    int bb = b & 255;
    double a = 0.0;
    for (int i = bb * 256 + t; i < DF * DM; i += 65536) a += (double)fabsf(src[i]);
    sd[t] = a; __syncthreads();
    for (int o = 128; o; o >>= 1) { if (t < o) sd[t] += sd[t + o]; __syncthreads(); }
    if (t == 0) g_part[b] = sd[0];
}

__global__ void k_final() {
    __shared__ double sd[256];
    int t = threadIdx.x;
    sd[t] = g_part[t]; __syncthreads();
    for (int o = 128; o; o >>= 1) { if (t < o) sd[t] += sd[t + o]; __syncthreads(); }
    if (t == 0) g_ws[0] = fmaxf((float)(sd[0] / (double)(DF * DM)), EPSF);
    __syncthreads();
    sd[t] = g_part[256 + t]; __syncthreads();
    for (int o = 128; o; o >>= 1) { if (t < o) sd[t] += sd[t + o]; __syncthreads(); }
    if (t == 0) g_ws[1] = fmaxf((float)(sd[0] / (double)(DF * DM)), EPSF);
}

__global__ void k_tern(const float* wu, const float* wd) {
    int i = blockIdx.x * 256 + threadIdx.x;
    float ws, v; int8_t* dst;
    if (i < DF * DM) { ws = g_ws[0]; v = wu[i]; dst = (int8_t*)g_wu_raw + i; }
    else             { ws = g_ws[1]; v = wd[i - DF * DM]; dst = (int8_t*)g_wd_raw + (i - DF * DM); }
    float q = fminf(fmaxf(rintf(v / ws), -1.f), 1.f);
    *dst = (int8_t)(int)q;
}

__global__ void k_xquant(const float* x) {
    int wid = threadIdx.x >> 5, lane = threadIdx.x & 31;
    int row = blockIdx.x * 8 + wid;
    const float4* xr = (const float4*)(x + (size_t)row * DM);
    float4 v[4]; float am = 0.f;
#pragma unroll
    for (int j = 0; j < 4; j++) {
        v[j] = xr[lane + 32 * j];
        am = fmaxf(am, fmaxf(fmaxf(fabsf(v[j].x), fabsf(v[j].y)), fmaxf(fabsf(v[j].z), fabsf(v[j].w))));
    }
#pragma unroll
    for (int o = 16; o; o >>= 1) am = fmaxf(am, __shfl_xor_sync(0xffffffffu, am, o));
    float xsc = 127.0f / fmaxf(am, EPSF);
    if (lane == 0) { g_xs[row] = xsc; g_rowmax[row] = 0; }
    uchar4* op = (uchar4*)((int8_t*)g_xq_raw + (size_t)row * DM);
#pragma unroll
    for (int j = 0; j < 4; j++) {
        int q0 = (int)fminf(fmaxf(rintf(v[j].x * xsc), -128.f), 127.f);
        int q1 = (int)fminf(fmaxf(rintf(v[j].y * xsc), -128.f), 127.f);
        int q2 = (int)fminf(fmaxf(rintf(v[j].z * xsc), -128.f), 127.f);
        int q3 = (int)fminf(fmaxf(rintf(v[j].w * xsc), -128.f), 127.f);
        op[lane + 32 * j] = make_uchar4((unsigned char)q0, (unsigned char)q1,
                                        (unsigned char)q2, (unsigned char)q3);
    }
}

__global__ void k_requant() {
    int wid = threadIdx.x >> 5, lane = threadIdx.x & 31;
    int row = blockIdx.x * 8 + wid;
    float clipped = fmaxf((float)g_rowmax[row], EPSF);
    float s = 127.0f / clipped;
    if (lane == 0) g_hs[row] = clipped / 127.0f;
    const uint4* hr = (const uint4*)((const char*)g_h_raw + (size_t)row * DF);
    uint4* op = (uint4*)((char*)g_hq_raw + (size_t)row * DF);
#pragma unroll
    for (int j = 0; j < 4; j++) {
        uint4 w = hr[lane + 32 * j];
        uint32_t in[4] = {w.x, w.y, w.z, w.w};
        uint32_t out[4];
#pragma unroll
        for (int k = 0; k < 4; k++) {
            uint32_t b = in[k], o = 0;
#pragma unroll
            for (int u = 0; u < 4; u++) {
                float hv = (float)((b >> (8 * u)) & 0xFF);            // h in 0..127
                uint32_t q = (uint32_t)(int)fminf(rintf(hv * s), 127.f);
                o |= (q & 0xFF) << (8 * u);
            }
            out[k] = o;
        }
        op[lane + 32 * j] = make_uint4(out[0], out[1], out[2], out[3]);
    }
}

// ---------------- int8 GEMM: C[128x128] = A[128,K] * B[128,K]^T ----------------
// warp grid 4(M) x 2(N); warp tile 32x64; mma m16n8k32 s8.s8.s32
// __launch_bounds__(256, 2): cap regs at 128 so 2 CTAs co-reside per SM.
__global__ void __launch_bounds__(256, 2) k_gemm(int K, int ntiles, int mode, float* OUT) {
    extern __shared__ char smem[];
    const uint32_t sb = smem_u32(smem);
    const int tid = threadIdx.x, lane = tid & 31, wid = tid >> 5;
    const int bid = blockIdx.x, mt = bid / ntiles, nt = bid % ntiles;
    const int m0 = mt * 128, n0 = nt * 128;
    const int wm = wid >> 1, wn = wid & 1;

    const int8_t* Ag = (mode == 1) ? (const int8_t*)g_xq_raw : (const int8_t*)g_hq_raw;
    const int8_t* Bg = (mode == 1) ? (const int8_t*)g_wu_raw : (const int8_t*)g_wd_raw;

    // ---- cp.async slots: 2 A granules + 2 B granules (16B) per thread ----
    const int8_t* srcA[2]; const int8_t* srcB[2];
    uint32_t dstA[2], dstB[2];
#pragma unroll
    for (int i = 0; i < 2; i++) {
        int G = tid + i * 256;                         // 0..511
        int r = G >> 2, ck = G & 3;                    // row 0..127, 16B chunk 0..3
        uint32_t phys = ((uint32_t)(ck ^ ((r >> 1) & 3))) << 4;
        dstA[i] = (uint32_t)r * 64 + phys;
        dstB[i] = 8192u + (uint32_t)r * 64 + phys;
        srcA[i] = Ag + (size_t)(m0 + r) * K + ck * 16;
        srcB[i] = Bg + (size_t)(n0 + r) * K + ck * 16;
    }

    // ---- ldmatrix lane precompute ----
    const int matrow = lane & 7, matsel = lane >> 3;
    const uint32_t kb16 = (uint32_t)(matsel >> 1);     // 16B half within k32
    const int r8 = (matsel & 1) * 8;
    uint32_t aTerm[2], aSw[2], bTerm[4], bSw[4];
#pragma unroll
    for (int f = 0; f < 2; f++) {
        int r = wm * 32 + f * 16 + r8 + matrow;
        aTerm[f] = (uint32_t)r * 64; aSw[f] = (uint32_t)((r >> 1) & 3);
    }
#pragma unroll
    for (int p = 0; p < 4; p++) {
        int r = wn * 64 + p * 16 + r8 + matrow;
        bTerm[p] = (uint32_t)r * 64; bSw[p] = (uint32_t)((r >> 1) & 3);
    }

    int acc[2][8][4];
#pragma unroll
    for (int f = 0; f < 2; f++)
#pragma unroll
        for (int j = 0; j < 8; j++)
#pragma unroll
            for (int k = 0; k < 4; k++) acc[f][j][k] = 0;

    const int nch = K / 64;
    // prologue: fill 3 stages
#pragma unroll
    for (int c = 0; c < 3; c++) {
        uint32_t base = sb + (uint32_t)(c & 3) * STG;
        size_t ko = (size_t)c * 64;
#pragma unroll
        for (int i = 0; i < 2; i++) cpasync16(base + dstA[i], srcA[i] + ko);
#pragma unroll
        for (int i = 0; i < 2; i++) cpasync16(base + dstB[i], srcB[i] + ko);
        CP_COMMIT();
    }

    for (int c = 0; c < nch; c++) {
        CP_WAIT(2);
        __syncthreads();
        // ---- issue next load FIRST (stage (c+3)&3 == (c-1)&3; barrier proved it
        //      was fully consumed in iteration c-1) so LSU overlaps the MMA block.
        int nx = c + 3;
        if (nx < nch) {
            uint32_t nb = sb + (uint32_t)(nx & 3) * STG;
            size_t ko = (size_t)nx * 64;
#pragma unroll
            for (int i = 0; i < 2; i++) cpasync16(nb + dstA[i], srcA[i] + ko);
#pragma unroll
            for (int i = 0; i < 2; i++) cpasync16(nb + dstB[i], srcB[i] + ko);
        }
        CP_COMMIT();
        // ---- compute stage c&3 : two k32 steps ----
        uint32_t base = sb + (uint32_t)(c & 3) * STG;
#pragma unroll
        for (int ks = 0; ks < 2; ks++) {
            uint32_t av[2][4], bv[4][4];
            uint32_t ck = (uint32_t)(ks * 2) + kb16;
#pragma unroll
            for (int f = 0; f < 2; f++) {
                uint32_t ad = base + aTerm[f] + ((ck ^ aSw[f]) << 4);
                LDMATRIX_X4(av[f], ad);
            }
#pragma unroll
            for (int p = 0; p < 4; p++) {
                uint32_t bd = base + 8192u + bTerm[p] + ((ck ^ bSw[p]) << 4);
                LDMATRIX_X4(bv[p], bd);
            }
#pragma unroll
            for (int f = 0; f < 2; f++)
#pragma unroll
                for (int j = 0; j < 8; j++) {
                    int p = j >> 1, o = j & 1;
                    IMMA(acc[f][j], av[f], bv[p][o], bv[p][o + 2]);
                }
        }
    }
    CP_WAIT(0);
    __syncthreads();

    // ---- epilogue ----
    const int g = lane >> 2, q4 = lane & 3;     // group row, in-group col pair
    if (mode == 1) {
        const float ws0 = g_ws[0];
        int lmax[2][2] = {{0, 0}, {0, 0}};
        int8_t* tile = (int8_t*)smem;           // 128x128 s8 staging
#pragma unroll
        for (int f = 0; f < 2; f++) {
            int rl0 = wm * 32 + f * 16 + g;
            float sc0 = ws0 / g_xs[m0 + rl0];
            float sc1 = ws0 / g_xs[m0 + rl0 + 8];
#pragma unroll
            for (int j = 0; j < 8; j++) {
                int col = wn * 64 + j * 8 + q4 * 2;
                int q0 = (int)fminf(rintf(fmaxf((float)acc[f][j][0] * sc0, 0.f)), 127.f);
                int q1 = (int)fminf(rintf(fmaxf((float)acc[f][j][1] * sc0, 0.f)), 127.f);
                int q2 = (int)fminf(rintf(fmaxf((float)acc[f][j][2] * sc1, 0.f)), 127.f);
                int q3 = (int)fminf(rintf(fmaxf((float)acc[f][j][3] * sc1, 0.f)), 127.f);
                lmax[f][0] = max(lmax[f][0], max(q0, q1));
                lmax[f][1] = max(lmax[f][1], max(q2, q3));
                *(char2*)(tile + rl0 * 128 + col)       = make_char2((char)q0, (char)q1);
                *(char2*)(tile + (rl0 + 8) * 128 + col) = make_char2((char)q2, (char)q3);
            }
        }
        // reduce row max across the 4 lanes of a group, then atomicMax
#pragma unroll
        for (int f = 0; f < 2; f++)
#pragma unroll
            for (int h = 0; h < 2; h++) {
                int v = lmax[f][h];
                v = max(v, __shfl_xor_sync(0xffffffffu, v, 1));
                v = max(v, __shfl_xor_sync(0xffffffffu, v, 2));
                if (q4 == 0) {
                    int row = m0 + wm * 32 + f * 16 + g + h * 8;
                    atomicMax(&g_rowmax[row], v);
                }
            }
        __syncthreads();
        // coalesced copy smem tile -> gmem h
        int8_t* hg = (int8_t*)g_h_raw;
#pragma unroll
        for (int i = 0; i < 4; i++) {
            int G = tid + i * 256;               // 0..1023
            int r = G >> 3, ch = G & 7;
            uint4 v = *(uint4*)(tile + r * 128 + ch * 16);
            *(uint4*)(hg + (size_t)(m0 + r) * DF + n0 + ch * 16) = v;
        }
    } else {
        const float ws1 = g_ws[1];
        const int ncols = ntiles * 128;
#pragma unroll
        for (int f = 0; f < 2; f++) {
            int rg0 = m0 + wm * 32 + f * 16 + g;
            float sc0 = ws1 * g_hs[rg0];
            float sc1 = ws1 * g_hs[rg0 + 8];
            float* o0 = OUT + (size_t)rg0 * ncols + n0 + wn * 64 + q4 * 2;
            float* o1 = OUT + (size_t)(rg0 + 8) * ncols + n0 + wn * 64 + q4 * 2;
#pragma unroll
            for (int j = 0; j < 8; j++) {
                float2 v0 = make_float2((float)acc[f][j][0] * sc0, (float)acc[f][j][1] * sc0);
                float2 v1 = make_float2((float)acc[f][j][2] * sc1, (float)acc[f][j][3] * sc1);
                *(float2*)(o0 + j * 8) = v0;
                *(float2*)(o1 + j * 8) = v1;
            }
        }
    }
}

// ---------------- launch ----------------
extern "C" void kernel_launch(void* const* d_in, const int* in_sizes, int n_in,
                              void* d_out, int out_size) {
    const float* x  = (const float*)d_in[0];
    const float* wu = (const float*)d_in[1];
    const float* wd = (const float*)d_in[2];
    float* out = (float*)d_out;

    cudaFuncSetAttribute(k_gemm, cudaFuncAttributeMaxDynamicSharedMemorySize, SMEM_SZ);

    k_absmean<<<512, 256>>>(wu, wd);
    k_final<<<1, 256>>>();
    k_tern<<<(2 * DF * DM) / 256, 256>>>(wu, wd);
    k_xquant<<<BTOK / 8, 256>>>(x);
    k_gemm<<<(BTOK / 128) * (DF / 128), 256, SMEM_SZ>>>(DM, DF / 128, 1, nullptr);
    k_requant<<<BTOK / 8, 256>>>();
    k_gemm<<<(BTOK / 128) * (DM / 128), 256, SMEM_SZ>>>(DF, DM / 128, 2, out);
}